// round 9
// baseline (speedup 1.0000x reference)
#include <cuda_runtime.h>
#include <cuda_fp16.h>
#include <cstdint>
#include <cstddef>

// Scatter-mean message passing via fp16-staged features + single-pass padded-CSR
// build + per-node gather-reduce (fp32 accumulation).
//   out[t] = mean over edges e with tgt[e]==t of x[src[e]]
// x: [N, 64] f32, edge_idx: [2, E] i32 (row 0 = src, row 1 = tgt)

#define F 64
#define MAX_N (1 << 17)      // >= 100000
#define SLOTS 32             // padded CSR row capacity = 128B = one L2 line
#define MAX_OVER 16384       // overflow spill capacity (correctness fallback)

typedef unsigned long long ull;

__device__ int g_cnt[MAX_N];                     // per-node edge count (true degree)
__device__ int g_sorted[(size_t)MAX_N * SLOTS];  // per-node src BYTE OFFSETS (src*128)
__device__ int g_over_src[MAX_OVER];             // overflow: src byte offsets
__device__ int g_over_tgt[MAX_OVER];
__device__ int g_over_cnt[1];
__device__ __align__(16) __half g_xh[(size_t)MAX_N * F];  // fp16 copy of x: 128B rows

__device__ __forceinline__ void spill_edge(int soff, int d) {
    int op = atomicAdd(&g_over_cnt[0], 1);
    if (op < MAX_OVER) { g_over_src[op] = soff; g_over_tgt[op] = d; }
}

// Streaming fp32 -> fp16 convert: 4 elements per thread.
__global__ void convert_kernel(const float4* __restrict__ x4, int total4) {
    int i = blockIdx.x * blockDim.x + threadIdx.x;
    if (i < total4) {
        float4 v = __ldg(&x4[i]);
        __half2 h0 = __floats2half2_rn(v.x, v.y);
        __half2 h1 = __floats2half2_rn(v.z, v.w);
        uint2 p;
        p.x = *(unsigned int*)&h0;
        p.y = *(unsigned int*)&h1;
        ((uint2*)g_xh)[i] = p;
    }
}

// Single build pass: 4 edges per thread via int4; 4 atomics issued before the
// 4 dependent scattered stores (atomic latency overlapped).
__global__ void fill_kernel(const int4* __restrict__ src4,
                            const int4* __restrict__ tgt4, int E4,
                            const int* __restrict__ src,
                            const int* __restrict__ tgt, int E) {
    int t = blockIdx.x * blockDim.x + threadIdx.x;
    if (t < E4) {
        int4 s = __ldg(&src4[t]);
        int4 d = __ldg(&tgt4[t]);
        int p0 = atomicAdd(&g_cnt[d.x], 1);
        int p1 = atomicAdd(&g_cnt[d.y], 1);
        int p2 = atomicAdd(&g_cnt[d.z], 1);
        int p3 = atomicAdd(&g_cnt[d.w], 1);
        if (p0 < SLOTS) g_sorted[(size_t)d.x * SLOTS + p0] = s.x << 7; else spill_edge(s.x << 7, d.x);
        if (p1 < SLOTS) g_sorted[(size_t)d.y * SLOTS + p1] = s.y << 7; else spill_edge(s.y << 7, d.y);
        if (p2 < SLOTS) g_sorted[(size_t)d.z * SLOTS + p2] = s.z << 7; else spill_edge(s.z << 7, d.z);
        if (p3 < SLOTS) g_sorted[(size_t)d.w * SLOTS + p3] = s.w << 7; else spill_edge(s.w << 7, d.w);
    }
    if (t == 0) {
        for (int e = E4 * 4; e < E; e++) {
            int d = tgt[e];
            int pos = atomicAdd(&g_cnt[d], 1);
            if (pos < SLOTS) g_sorted[(size_t)d * SLOTS + pos] = src[e] << 7;
            else spill_edge(src[e] << 7, d);
        }
    }
}

// One warp per node. Lane owns 4B (half2 = features 2l, 2l+1) of the 128B row:
// one warp LDG.32 = one L2 line per edge. R8 recipe: unroll 2, scalar
// warp-uniform index loads, 2 fp32 accumulators, high occupancy.
__global__ void __launch_bounds__(256)
aggregate_kernel(float2* __restrict__ out2, int N) {
    int n = (blockIdx.x * blockDim.x + threadIdx.x) >> 5;
    int lane = threadIdx.x & 31;
    if (n >= N) return;

    int count = g_cnt[n];
    int m = count < SLOTS ? count : SLOTS;
    const int* row = &g_sorted[(size_t)n * SLOTS];
    const char* xlane = (const char*)g_xh + (lane << 2);

    float ax0 = 0.f, ay0 = 0.f, ax1 = 0.f, ay1 = 0.f;

    int k = 0;
    for (; k + 2 <= m; k += 2) {
        int s0 = __ldg(&row[k + 0]);
        int s1 = __ldg(&row[k + 1]);
        __half2 h0 = *(const __half2*)(xlane + (size_t)(unsigned)s0);
        __half2 h1 = *(const __half2*)(xlane + (size_t)(unsigned)s1);
        float2 f0 = __half22float2(h0);
        float2 f1 = __half22float2(h1);
        ax0 += f0.x; ay0 += f0.y;
        ax1 += f1.x; ay1 += f1.y;
    }
    if (k < m) {
        int s = __ldg(&row[k]);
        float2 f = __half22float2(*(const __half2*)(xlane + (size_t)(unsigned)s));
        ax0 += f.x; ay0 += f.y;
    }

    // Overflow fallback (cold: only if some node's degree exceeded SLOTS).
    if (count > SLOTS) {
        int oc = g_over_cnt[0];
        for (int i = 0; i < oc; i++) {
            if (g_over_tgt[i] == n) {
                int s = g_over_src[i];
                float2 f = __half22float2(*(const __half2*)(xlane + (size_t)(unsigned)s));
                ax0 += f.x; ay0 += f.y;
            }
        }
    }

    float inv = count > 0 ? 1.0f / (float)count : 0.0f;
    float2 ov;
    ov.x = (ax0 + ax1) * inv;
    ov.y = (ay0 + ay1) * inv;
    out2[(size_t)n * 32 + lane] = ov;   // lane's float2 = features 2l, 2l+1
}

extern "C" void kernel_launch(void* const* d_in, const int* in_sizes, int n_in,
                              void* d_out, int out_size) {
    const float* x = (const float*)d_in[0];
    const int* edge_idx = (const int*)d_in[1];

    int E = in_sizes[1] / 2;
    int N = out_size / F;

    const int* src = edge_idx;       // row 0
    const int* tgt = edge_idx + E;   // row 1

    // Zero scratch counters via memset nodes.
    void* cnt_ptr = nullptr;
    void* over_ptr = nullptr;
    cudaGetSymbolAddress(&cnt_ptr, g_cnt);
    cudaGetSymbolAddress(&over_ptr, g_over_cnt);
    cudaMemsetAsync(cnt_ptr, 0, (size_t)N * sizeof(int));
    cudaMemsetAsync(over_ptr, 0, sizeof(int));

    const int T = 256;

    // fp16 staging of x
    int total4 = (N * F) / 4;
    convert_kernel<<<(total4 + T - 1) / T, T>>>((const float4*)x, total4);

    int E4 = E / 4;
    int fill_blocks = (E4 + T - 1) / T;
    if (fill_blocks < 1) fill_blocks = 1;
    fill_kernel<<<fill_blocks, T>>>((const int4*)src, (const int4*)tgt, E4,
                                    src, tgt, E);

    long long total = (long long)N * 32;
    aggregate_kernel<<<(int)((total + T - 1) / T), T>>>((float2*)d_out, N);
}

// round 10
// speedup vs baseline: 1.2403x; 1.2403x over previous
#include <cuda_runtime.h>
#include <cstdint>
#include <cstddef>

// Scatter-mean message passing via single-pass padded-CSR build + per-node gather-reduce.
//   out[t] = mean over edges e with tgt[e]==t of x[src[e]]
// x: [N, 64] f32, edge_idx: [2, E] i32 (row 0 = src, row 1 = tgt)

#define F 64
#define MAX_N (1 << 17)      // >= 100000
#define SLOTS 32             // padded CSR row capacity = 128B = one L2 line
#define MAX_OVER 16384       // overflow spill capacity (correctness fallback)
#define AGG_BLOCKS (148 * 8) // persistent grid: one wave at occ 8

typedef unsigned long long ull;

__device__ int g_cnt[MAX_N];                     // per-node edge count (true degree)
__device__ int g_sorted[(size_t)MAX_N * SLOTS];  // per-node src BYTE OFFSETS (src*256)
__device__ int g_over_src[MAX_OVER];             // overflow: src byte offsets
__device__ int g_over_tgt[MAX_OVER];
__device__ int g_over_cnt[1];

__device__ __forceinline__ void spill_edge(int soff, int d) {
    int op = atomicAdd(&g_over_cnt[0], 1);
    if (op < MAX_OVER) { g_over_src[op] = soff; g_over_tgt[op] = d; }
}

// Single build pass: 4 edges per thread via int4; 4 atomics issued before the
// 4 dependent scattered stores (atomic latency overlapped).
__global__ void fill_kernel(const int4* __restrict__ src4,
                            const int4* __restrict__ tgt4, int E4,
                            const int* __restrict__ src,
                            const int* __restrict__ tgt, int E) {
    int t = blockIdx.x * blockDim.x + threadIdx.x;
    if (t < E4) {
        int4 s = __ldg(&src4[t]);
        int4 d = __ldg(&tgt4[t]);
        int p0 = atomicAdd(&g_cnt[d.x], 1);
        int p1 = atomicAdd(&g_cnt[d.y], 1);
        int p2 = atomicAdd(&g_cnt[d.z], 1);
        int p3 = atomicAdd(&g_cnt[d.w], 1);
        if (p0 < SLOTS) g_sorted[(size_t)d.x * SLOTS + p0] = s.x << 8; else spill_edge(s.x << 8, d.x);
        if (p1 < SLOTS) g_sorted[(size_t)d.y * SLOTS + p1] = s.y << 8; else spill_edge(s.y << 8, d.y);
        if (p2 < SLOTS) g_sorted[(size_t)d.z * SLOTS + p2] = s.z << 8; else spill_edge(s.z << 8, d.z);
        if (p3 < SLOTS) g_sorted[(size_t)d.w * SLOTS + p3] = s.w << 8; else spill_edge(s.w << 8, d.w);
    }
    if (t == 0) {
        for (int e = E4 * 4; e < E; e++) {
            int d = tgt[e];
            int pos = atomicAdd(&g_cnt[d], 1);
            if (pos < SLOTS) g_sorted[(size_t)d * SLOTS + pos] = src[e] << 8;
            else spill_edge(src[e] << 8, d);
        }
    }
}

__device__ __forceinline__ ull f2add(ull a, ull b) {
    ull r;
    asm("add.rn.f32x2 %0, %1, %2;" : "=l"(r) : "l"(a), "l"(b));
    return r;
}
__device__ __forceinline__ ull f2mul(ull a, ull b) {
    ull r;
    asm("mul.rn.f32x2 %0, %1, %2;" : "=l"(r) : "l"(a), "l"(b));
    return r;
}
// L2-only gather (skip L1 allocation: gathered rows have ~no per-SM reuse).
__device__ __forceinline__ ull ldg_cg64(const void* p) {
    ull r;
    asm volatile("ld.global.cg.u64 %0, [%1];" : "=l"(r) : "l"(p));
    return r;
}

// One warp per node, persistent grid-stride over nodes (one wave, no
// wave-transition overhead, balanced tail). Lane owns 8B (float2) of the
// 256B row. R8 recipe: unroll 2, scalar warp-uniform idx loads, 2 accumulators.
__global__ void __launch_bounds__(256)
aggregate_kernel(const char* __restrict__ xbase,
                 float2* __restrict__ out2, int N) {
    int warp_id = (blockIdx.x * blockDim.x + threadIdx.x) >> 5;
    int lane = threadIdx.x & 31;
    int nwarps = (gridDim.x * blockDim.x) >> 5;
    const char* xlane = xbase + (lane << 3);

    for (int n = warp_id; n < N; n += nwarps) {
        int count = g_cnt[n];
        int m = count < SLOTS ? count : SLOTS;
        const int* row = &g_sorted[(size_t)n * SLOTS];

        ull a0 = 0, a1 = 0;

        int k = 0;
        for (; k + 2 <= m; k += 2) {
            int s0 = __ldg(&row[k + 0]);
            int s1 = __ldg(&row[k + 1]);
            ull v0 = ldg_cg64(xlane + (size_t)(unsigned)s0);
            ull v1 = ldg_cg64(xlane + (size_t)(unsigned)s1);
            a0 = f2add(a0, v0);
            a1 = f2add(a1, v1);
        }
        if (k < m) {
            int s = __ldg(&row[k]);
            a0 = f2add(a0, ldg_cg64(xlane + (size_t)(unsigned)s));
        }

        // Overflow fallback (cold: only if some node's degree exceeded SLOTS).
        if (count > SLOTS) {
            int oc = g_over_cnt[0];
            for (int i = 0; i < oc; i++) {
                if (g_over_tgt[i] == n) {
                    int s = g_over_src[i];
                    a0 = f2add(a0, ldg_cg64(xlane + (size_t)(unsigned)s));
                }
            }
        }

        a0 = f2add(a0, a1);

        float inv = count > 0 ? 1.0f / (float)count : 0.0f;
        ull inv2;
        asm("mov.b64 %0, {%1, %1};" : "=l"(inv2) : "f"(inv));
        ull o = f2mul(a0, inv2);

        unsigned int lo, hi;
        asm("mov.b64 {%0, %1}, %2;" : "=r"(lo), "=r"(hi) : "l"(o));
        float2 ov;
        ov.x = __uint_as_float(lo);
        ov.y = __uint_as_float(hi);
        out2[(size_t)n * 32 + lane] = ov;
    }
}

extern "C" void kernel_launch(void* const* d_in, const int* in_sizes, int n_in,
                              void* d_out, int out_size) {
    const float* x = (const float*)d_in[0];
    const int* edge_idx = (const int*)d_in[1];

    int E = in_sizes[1] / 2;
    int N = out_size / F;

    const int* src = edge_idx;       // row 0
    const int* tgt = edge_idx + E;   // row 1

    // Zero scratch counters via memset nodes.
    void* cnt_ptr = nullptr;
    void* over_ptr = nullptr;
    cudaGetSymbolAddress(&cnt_ptr, g_cnt);
    cudaGetSymbolAddress(&over_ptr, g_over_cnt);
    cudaMemsetAsync(cnt_ptr, 0, (size_t)N * sizeof(int));
    cudaMemsetAsync(over_ptr, 0, sizeof(int));

    const int T = 256;

    int E4 = E / 4;
    int fill_blocks = (E4 + T - 1) / T;
    if (fill_blocks < 1) fill_blocks = 1;
    fill_kernel<<<fill_blocks, T>>>((const int4*)src, (const int4*)tgt, E4,
                                    src, tgt, E);

    // Persistent one-wave grid (cap at what N needs).
    long long warps_needed = (long long)N;
    long long blocks_needed = (warps_needed * 32 + T - 1) / T;
    int agg_blocks = blocks_needed < AGG_BLOCKS ? (int)blocks_needed : AGG_BLOCKS;
    aggregate_kernel<<<agg_blocks, T>>>((const char*)x, (float2*)d_out, N);
}